// round 8
// baseline (speedup 1.0000x reference)
#include <cuda_runtime.h>

// Problem constants
constexpr int Pn   = 48 * 48;   // 2304 spatial positions
constexpr int CX_  = 512;
constexpr int CF_  = 256;
constexpr int HID_ = 256;
constexpr int OUT_ = 512;
constexpr int B_   = 4;
constexpr int N_   = 4;
constexpr int BN_  = B_ * N_;   // 16

// Scratch (device globals: allocation inside kernel_launch is forbidden)
__device__ float g_Q1[(size_t)BN_ * HID_ * Pn];   //  37.7 MB
__device__ float g_K1[(size_t)B_  * HID_ * Pn];   //   9.4 MB (per-b: flow broadcast over n)
__device__ float g_Q2[(size_t)B_  * HID_ * Pn];   //   9.4 MB
__device__ float g_K2[(size_t)BN_ * HID_ * Pn];   //  37.7 MB
__device__ float g_S [(size_t)BN_ * Pn * Pn];     // 339.7 MB (scores/attn, reused by both layers)
__device__ float g_WR[(size_t)BN_ * CF_ * Pn];    //  37.7 MB
__device__ float g_WL[(size_t)BN_ * CX_ * Pn];    //  75.5 MB

// ---------------------------------------------------------------------------
// Batched SGEMM: C[z] = op(A[z]) * op(B[z]) (+ bias[m]) (+= existing C)
//   TRA=false: A is M x K row-major (A[m*lda+k]);  TRA=true: A is K x M (A[k*lda+m])
//   TRB=false: B is K x N row-major (B[k*ldb+n]);  TRB=true: B is N x K (B[n*ldb+k])
// Batch offsets: A += (z/dA)*sA, B += (z/dB)*sB, C += z*sC
// Requirements (all satisfied here): M,N multiples of 128; K multiple of 8;
// all leading dims multiples of 4; pointers 16B aligned.
// Tile: 128x128, TK=8, 256 threads, 8x8 per thread, double-buffered smem.
// ---------------------------------------------------------------------------
template<bool TRA, bool TRB, bool BIAS, bool ACCUM>
__global__ __launch_bounds__(256, 2)
void gemm128(const float* __restrict__ Ag, int lda, long long sA, int dA,
             const float* __restrict__ Bg, int ldb, long long sB, int dB,
             const float* __restrict__ bias,
             float* __restrict__ Cg, int ldc, long long sC,
             int K)
{
    const int z = blockIdx.z;
    const float* A = Ag + (long long)(z / dA) * sA;
    const float* B = Bg + (long long)(z / dB) * sB;
    float* C = Cg + (long long)z * sC;

    __shared__ float As[2][8][132];   // padded to 132 to dodge bank conflicts
    __shared__ float Bs[2][8][132];

    const int tid = threadIdx.x;
    const int tx  = tid & 15;
    const int ty  = tid >> 4;
    const int m0  = blockIdx.y * 128;
    const int n0  = blockIdx.x * 128;

    // loader index sets
    const int krow  = tid >> 5;          // 0..7   (direct: 8 k-rows x 128 contiguous)
    const int kcol4 = (tid & 31) << 2;   // 0..124
    const int arow  = tid >> 1;          // 0..127 (transpose-on-load: 128 rows x 8 k)
    const int acol4 = (tid & 1) << 2;    // 0 or 4

    float acc[8][8];
    #pragma unroll
    for (int i = 0; i < 8; ++i)
        #pragma unroll
        for (int j = 0; j < 8; ++j)
            acc[i][j] = 0.0f;

    auto loadA = [&](int kt, int buf) {
        if (TRA) {
            // A stored K x M: row k, 128 contiguous m -> float4 direct
            float4 v = *reinterpret_cast<const float4*>(
                A + (size_t)(kt * 8 + krow) * lda + m0 + kcol4);
            *reinterpret_cast<float4*>(&As[buf][krow][kcol4]) = v;
        } else {
            // A stored M x K: read 8 k's per m-row, scatter-transpose
            float4 v = *reinterpret_cast<const float4*>(
                A + (size_t)(m0 + arow) * lda + kt * 8 + acol4);
            As[buf][acol4 + 0][arow] = v.x;
            As[buf][acol4 + 1][arow] = v.y;
            As[buf][acol4 + 2][arow] = v.z;
            As[buf][acol4 + 3][arow] = v.w;
        }
    };
    auto loadB = [&](int kt, int buf) {
        if (!TRB) {
            float4 v = *reinterpret_cast<const float4*>(
                B + (size_t)(kt * 8 + krow) * ldb + n0 + kcol4);
            *reinterpret_cast<float4*>(&Bs[buf][krow][kcol4]) = v;
        } else {
            float4 v = *reinterpret_cast<const float4*>(
                B + (size_t)(n0 + arow) * ldb + kt * 8 + acol4);
            Bs[buf][acol4 + 0][arow] = v.x;
            Bs[buf][acol4 + 1][arow] = v.y;
            Bs[buf][acol4 + 2][arow] = v.z;
            Bs[buf][acol4 + 3][arow] = v.w;
        }
    };

    loadA(0, 0);
    loadB(0, 0);
    __syncthreads();

    const int nkt = K >> 3;
    for (int kt = 0; kt < nkt; ++kt) {
        const int cur = kt & 1;
        if (kt + 1 < nkt) {            // prefetch next tile into the other buffer
            loadA(kt + 1, cur ^ 1);
            loadB(kt + 1, cur ^ 1);
        }
        #pragma unroll
        for (int kk = 0; kk < 8; ++kk) {
            float4 a0 = *reinterpret_cast<const float4*>(&As[cur][kk][ty << 2]);
            float4 a1 = *reinterpret_cast<const float4*>(&As[cur][kk][64 + (ty << 2)]);
            float4 b0 = *reinterpret_cast<const float4*>(&Bs[cur][kk][tx << 2]);
            float4 b1 = *reinterpret_cast<const float4*>(&Bs[cur][kk][64 + (tx << 2)]);
            float a[8] = {a0.x, a0.y, a0.z, a0.w, a1.x, a1.y, a1.z, a1.w};
            float b[8] = {b0.x, b0.y, b0.z, b0.w, b1.x, b1.y, b1.z, b1.w};
            #pragma unroll
            for (int i = 0; i < 8; ++i)
                #pragma unroll
                for (int j = 0; j < 8; ++j)
                    acc[i][j] = fmaf(a[i], b[j], acc[i][j]);
        }
        __syncthreads();
    }

    // epilogue
    #pragma unroll
    for (int i = 0; i < 8; ++i) {
        const int m = m0 + ((i < 4) ? (ty * 4 + i) : (64 + ty * 4 + i - 4));
        const float bv = BIAS ? bias[m] : 0.0f;
        float* crow = C + (size_t)m * ldc + n0;
        float4 v0 = make_float4(acc[i][0] + bv, acc[i][1] + bv,
                                acc[i][2] + bv, acc[i][3] + bv);
        float4 v1 = make_float4(acc[i][4] + bv, acc[i][5] + bv,
                                acc[i][6] + bv, acc[i][7] + bv);
        if (ACCUM) {
            float4 o0 = *reinterpret_cast<const float4*>(crow + (tx << 2));
            float4 o1 = *reinterpret_cast<const float4*>(crow + 64 + (tx << 2));
            v0.x += o0.x; v0.y += o0.y; v0.z += o0.z; v0.w += o0.w;
            v1.x += o1.x; v1.y += o1.y; v1.z += o1.z; v1.w += o1.w;
        }
        *reinterpret_cast<float4*>(crow + (tx << 2)) = v0;
        *reinterpret_cast<float4*>(crow + 64 + (tx << 2)) = v1;
    }
}

// ---------------------------------------------------------------------------
// Row softmax over g_S: grid (Pn, BN_), 256 threads, row kept in registers
// (Pn = 2304 = 9 * 256 exactly)
// ---------------------------------------------------------------------------
__global__ __launch_bounds__(256)
void softmax_rows(float* __restrict__ S)
{
    const int tid = threadIdx.x;
    const size_t base = ((size_t)blockIdx.y * Pn + blockIdx.x) * Pn;

    float r[9];
    float mx = -3.4e38f;
    #pragma unroll
    for (int j = 0; j < 9; ++j) {
        r[j] = S[base + tid + j * 256];
        mx = fmaxf(mx, r[j]);
    }

    __shared__ float sred[8];
    #pragma unroll
    for (int o = 16; o > 0; o >>= 1)
        mx = fmaxf(mx, __shfl_xor_sync(0xffffffffu, mx, o));
    if ((tid & 31) == 0) sred[tid >> 5] = mx;
    __syncthreads();
    mx = sred[0];
    #pragma unroll
    for (int w = 1; w < 8; ++w) mx = fmaxf(mx, sred[w]);

    float s = 0.0f;
    #pragma unroll
    for (int j = 0; j < 9; ++j) {
        r[j] = __expf(r[j] - mx);
        s += r[j];
    }
    #pragma unroll
    for (int o = 16; o > 0; o >>= 1)
        s += __shfl_xor_sync(0xffffffffu, s, o);
    __syncthreads();
    if ((tid & 31) == 0) sred[tid >> 5] = s;
    __syncthreads();
    s = 0.0f;
    #pragma unroll
    for (int w = 0; w < 8; ++w) s += sred[w];

    const float inv = 1.0f / s;
    #pragma unroll
    for (int j = 0; j < 9; ++j)
        S[base + tid + j * 256] = r[j] * inv;
}

// ---------------------------------------------------------------------------
// Launch sequence (all on default stream => serialized, graph-capturable)
// ---------------------------------------------------------------------------
extern "C" void kernel_launch(void* const* d_in, const int* in_sizes, int n_in,
                              void* d_out, int out_size)
{
    const float* mv  = (const float*)d_in[0];   // [4,4,512,48,48] -> [16,512,P]
    const float* ff  = (const float*)d_in[1];   // [4,256,48,48]   -> [4,256,P]
    const float* wq1 = (const float*)d_in[2];
    const float* bq1 = (const float*)d_in[3];
    const float* wk1 = (const float*)d_in[4];
    const float* bk1 = (const float*)d_in[5];
    const float* wq2 = (const float*)d_in[6];
    const float* bq2 = (const float*)d_in[7];
    const float* wk2 = (const float*)d_in[8];
    const float* bk2 = (const float*)d_in[9];
    const float* wdr = (const float*)d_in[10];  // [512, 1536]
    const float* bdr = (const float*)d_in[11];
    float* out = (float*)d_out;                 // [16, 512, P]

    float *Q1, *K1, *Q2, *K2, *S, *WR, *WL;
    cudaGetSymbolAddress((void**)&Q1, g_Q1);
    cudaGetSymbolAddress((void**)&K1, g_K1);
    cudaGetSymbolAddress((void**)&Q2, g_Q2);
    cudaGetSymbolAddress((void**)&K2, g_K2);
    cudaGetSymbolAddress((void**)&S,  g_S);
    cudaGetSymbolAddress((void**)&WR, g_WR);
    cudaGetSymbolAddress((void**)&WL, g_WL);

    const long long sMV = (long long)CX_  * Pn;   // per-image memory slice
    const long long sFF = (long long)CF_  * Pn;   // per-b flow slice
    const long long sH  = (long long)HID_ * Pn;
    const long long sS  = (long long)Pn   * Pn;
    const long long sWR = (long long)CF_  * Pn;
    const long long sWL = (long long)CX_  * Pn;
    const long long sO  = (long long)OUT_ * Pn;

    // --- projections ---
    // Q1[z] = wq1 @ mv[z] + bq1            [256 x P], K=512, batch 16
    gemm128<false, false, true, false><<<dim3(18, 2, 16), 256>>>(
        wq1, CX_, 0LL, 1,  mv, Pn, sMV, 1,  bq1,  Q1, Pn, sH, CX_);
    // K1[b] = wk1 @ ff[b] + bk1            [256 x P], K=256, batch 4 (per-b only)
    gemm128<false, false, true, false><<<dim3(18, 2, 4), 256>>>(
        wk1, CF_, 0LL, 1,  ff, Pn, sFF, 1,  bk1,  K1, Pn, sH, CF_);
    // Q2[b] = wq2 @ ff[b] + bq2            [256 x P], K=256, batch 4
    gemm128<false, false, true, false><<<dim3(18, 2, 4), 256>>>(
        wq2, CF_, 0LL, 1,  ff, Pn, sFF, 1,  bq2,  Q2, Pn, sH, CF_);
    // K2[z] = wk2 @ mv[z] + bk2            [256 x P], K=512, batch 16
    gemm128<false, false, true, false><<<dim3(18, 2, 16), 256>>>(
        wk2, CX_, 0LL, 1,  mv, Pn, sMV, 1,  bk2,  K2, Pn, sH, CX_);

    // --- layer 1: scores = Q1^T K1 ; softmax ; WR = ff @ attn^T ---
    gemm128<true, false, false, false><<<dim3(18, 18, 16), 256>>>(
        Q1, Pn, sH, 1,  K1, Pn, sH, 4,  nullptr,  S, Pn, sS, HID_);
    softmax_rows<<<dim3(Pn, BN_), 256>>>(S);
    gemm128<false, true, false, false><<<dim3(18, 2, 16), 256>>>(
        ff, Pn, sFF, 4,  S, Pn, sS, 1,  nullptr,  WR, Pn, sWR, Pn);

    // --- layer 2: scores = Q2^T K2 ; softmax ; WL = mv @ attn^T ---
    gemm128<true, false, false, false><<<dim3(18, 18, 16), 256>>>(
        Q2, Pn, sH, 4,  K2, Pn, sH, 1,  nullptr,  S, Pn, sS, HID_);
    softmax_rows<<<dim3(Pn, BN_), 256>>>(S);
    gemm128<false, true, false, false><<<dim3(18, 4, 16), 256>>>(
        mv, Pn, sMV, 1,  S, Pn, sS, 1,  nullptr,  WL, Pn, sWL, Pn);

    // --- final 1x1 conv: out = wdr @ concat(mv, WL, ff, WR) + bdr ---
    // split into 4 accumulating GEMMs over the concat slices of wdr (ld = 1536)
    gemm128<false, false, true, false><<<dim3(18, 4, 16), 256>>>(
        wdr + 0,    2 * (CX_ + CF_), 0LL, 1,  mv, Pn, sMV, 1,  bdr,
        out, Pn, sO, CX_);
    gemm128<false, false, false, true><<<dim3(18, 4, 16), 256>>>(
        wdr + 512,  2 * (CX_ + CF_), 0LL, 1,  WL, Pn, sWL, 1,  nullptr,
        out, Pn, sO, CX_);
    gemm128<false, false, false, true><<<dim3(18, 4, 16), 256>>>(
        wdr + 1024, 2 * (CX_ + CF_), 0LL, 1,  ff, Pn, sFF, 4,  nullptr,
        out, Pn, sO, CF_);
    gemm128<false, false, false, true><<<dim3(18, 4, 16), 256>>>(
        wdr + 1280, 2 * (CX_ + CF_), 0LL, 1,  WR, Pn, sWR, 1,  nullptr,
        out, Pn, sO, CF_);
}

// round 11
// speedup vs baseline: 2.0464x; 2.0464x over previous
#include <cuda_runtime.h>
#include <cstdint>

// ---------------------------------------------------------------------------
// Arch gate: tcgen05 only exists on the arch-specific (sm_103a) target. The
// harness also compiles a plain compute_103 target, which must fall back.
// ---------------------------------------------------------------------------
#if defined(__CUDA_ARCH_FEAT_SM103_ALL) || defined(__CUDA_ARCH_FEAT_SM100_ALL) || \
    defined(__CUDA_ARCH_SPECIFIC__) || defined(__CUDA_ARCH_FAMILY_SPECIFIC__)
#define USE_TC 1
#else
#define USE_TC 0
#endif

// ---------------------------------------------------------------------------
// Problem constants
// ---------------------------------------------------------------------------
constexpr int Pn   = 48 * 48;   // 2304
constexpr int CX_  = 512;
constexpr int CF_  = 256;
constexpr int HID_ = 256;
constexpr int OUT_ = 512;
constexpr int BN_  = 16;

// ---------------------------------------------------------------------------
// Scratch (device globals; no allocation allowed). Everything K-major for its
// consumer GEMM.
// ---------------------------------------------------------------------------
__device__ float g_mvT[(size_t)BN_ * Pn * CX_];   // [z][p][cx]
__device__ float g_ffT[(size_t)4   * Pn * CF_];   // [b][p][cf]
__device__ float g_Q1t[(size_t)BN_ * Pn * HID_];  // [z][p][h]
__device__ float g_K1t[(size_t)4   * Pn * HID_];
__device__ float g_Q2t[(size_t)4   * Pn * HID_];
__device__ float g_K2t[(size_t)BN_ * Pn * HID_];
__device__ float g_S  [(size_t)BN_ * Pn * Pn];    // scores/attn (both layers)
__device__ float g_WRT[(size_t)BN_ * Pn * CF_];   // [z][p][cf]
__device__ float g_WLT[(size_t)BN_ * Pn * CX_];   // [z][p][cx]

// ---------------------------------------------------------------------------
// PTX helpers (all __forceinline__, unreferenced on non-a targets => not emitted)
// ---------------------------------------------------------------------------
__device__ __forceinline__ uint32_t smem_u32(const void* p) {
    uint32_t a;
    asm("{ .reg .u64 t; cvta.to.shared.u64 t, %1; cvt.u32.u64 %0, t; }"
        : "=r"(a) : "l"(p));
    return a;
}
__device__ __forceinline__ float to_tf32(float x) {
    uint32_t u;
    asm("cvt.rna.tf32.f32 %0, %1;" : "=r"(u) : "f"(x));
    return __uint_as_float(u);
}

#define MBAR_INIT(a, c) \
    asm volatile("mbarrier.init.shared.b64 [%0], %1;" :: "r"(a), "r"(c) : "memory")
#define MBAR_ARRIVE(a) \
    asm volatile("mbarrier.arrive.shared.b64 _, [%0];" :: "r"(a) : "memory")
#define MBAR_WAIT(a, ph) do {                                                  \
    uint32_t _m = (a), _p = (ph), _d = 0;                                      \
    while (!_d) {                                                              \
        asm volatile("{\n\t.reg .pred p;\n\t"                                  \
            "mbarrier.try_wait.parity.acquire.cta.shared::cta.b64 p, [%1], %2, 0x989680;\n\t" \
            "selp.b32 %0, 1, 0, p;\n\t}"                                       \
            : "=r"(_d) : "r"(_m), "r"(_p) : "memory");                         \
    } } while (0)

#define TC_ALLOC(sa, nc) \
    asm volatile("tcgen05.alloc.cta_group::1.sync.aligned.shared::cta.b32 [%0], %1;" \
        :: "r"(sa), "r"((uint32_t)(nc)) : "memory")
#define TC_RELINQ() \
    asm volatile("tcgen05.relinquish_alloc_permit.cta_group::1.sync.aligned;")
#define TC_DEALLOC(tm, nc) \
    asm volatile("tcgen05.dealloc.cta_group::1.sync.aligned.b32 %0, %1;" \
        :: "r"(tm), "r"((uint32_t)(nc)))
#define TC_COMMIT(mb) \
    asm volatile("tcgen05.commit.cta_group::1.mbarrier::arrive::one.shared::cluster.b64 [%0];" \
        :: "r"(mb) : "memory")
#define TC_FENCE_AFTER() asm volatile("tcgen05.fence::after_thread_sync;" ::: "memory")
#define TC_WAIT_LD()     asm volatile("tcgen05.wait::ld.sync.aligned;" ::: "memory")
#define FENCE_ASYNC()    asm volatile("fence.proxy.async.shared::cta;" ::: "memory")

#define TC_LD_X32(r, ta) \
    asm volatile("tcgen05.ld.sync.aligned.32x32b.x32.b32 " \
        "{%0,%1,%2,%3,%4,%5,%6,%7,%8,%9,%10,%11,%12,%13,%14,%15," \
        "%16,%17,%18,%19,%20,%21,%22,%23,%24,%25,%26,%27,%28,%29,%30,%31}, [%32];" \
        : "=r"((r)[0]),"=r"((r)[1]),"=r"((r)[2]),"=r"((r)[3]),   \
          "=r"((r)[4]),"=r"((r)[5]),"=r"((r)[6]),"=r"((r)[7]),   \
          "=r"((r)[8]),"=r"((r)[9]),"=r"((r)[10]),"=r"((r)[11]), \
          "=r"((r)[12]),"=r"((r)[13]),"=r"((r)[14]),"=r"((r)[15]),\
          "=r"((r)[16]),"=r"((r)[17]),"=r"((r)[18]),"=r"((r)[19]),\
          "=r"((r)[20]),"=r"((r)[21]),"=r"((r)[22]),"=r"((r)[23]),\
          "=r"((r)[24]),"=r"((r)[25]),"=r"((r)[26]),"=r"((r)[27]),\
          "=r"((r)[28]),"=r"((r)[29]),"=r"((r)[30]),"=r"((r)[31]) \
        : "r"(ta))

// idesc: D=F32(1<<4), A=TF32(2<<7), B=TF32(2<<10), N=128 (N/8 @17), M=128 (M/16 @24)
constexpr uint32_t IDESC_TF32 =
    (1u << 4) | (2u << 7) | (2u << 10) | ((128u / 8) << 17) | ((128u / 16) << 24);

__device__ __forceinline__ void mma_tf32(uint32_t d, uint64_t ad, uint64_t bd, bool acc) {
    asm volatile("{\n\t.reg .pred p;\n\tsetp.ne.u32 p, %5, 0;\n\t"
        "tcgen05.mma.cta_group::1.kind::tf32 [%0], %1, %2, %3, {%4,%4,%4,%4}, p;\n\t}"
        :: "r"(d), "l"(ad), "l"(bd), "r"(IDESC_TF32), "r"(0u), "r"(acc ? 1u : 0u)
        : "memory");
}

// SW128 K-major smem descriptor: layout=2, version=1, SBO=64, LBO=1
constexpr uint64_t DESC_BASE =
    (2ull << 61) | (1ull << 46) | (64ull << 32) | (1ull << 16);
__device__ __forceinline__ uint64_t sdesc(uint32_t addr) {
    return DESC_BASE | ((uint64_t)(addr >> 4) & 0x3FFFull);
}
__device__ __forceinline__ uint32_t sw128(uint32_t off) {
    return off ^ ((off >> 3) & 0x70);
}

// smem layout: 64B header (tmem ptr @0; mbars full[3]@8.., empty[3]@32.., done@56),
// then 1024-aligned data region: 3 stages x 64KB (Ahi|Alo|Bhi|Blo 16KB each).
constexpr int TILE_B    = 16384;
constexpr int STAGE_B   = 4 * TILE_B;
constexpr int NSTAGE    = 3;
constexpr int SMEM_DYN  = 1024 + NSTAGE * STAGE_B + 1024;

// ---------------------------------------------------------------------------
// Batched GEMM: D[m,n] = sum_k A[m,k] * B[n,k]; A,B K-major in gmem.
// Tile 128x128, K-chunk 32.  BIASM: 0 none, 1 bias[n], 2 bias[m].
// CONV: B rows gathered from concat(Bg=mvT | Bc1=WLT | Bc2=ffT | Bc3=WRT).
// sm_103a: tcgen05 3xTF32-split.  plain sm_103: FFMA fallback (same contract).
// ---------------------------------------------------------------------------
template<int BIASM, bool CONV>
__global__ void __launch_bounds__(256, 1)
tfgemm(const float* __restrict__ Ag, int lda, long long sA, int dA,
       const float* __restrict__ Bg, int ldb, long long sB, int dB,
       const float* __restrict__ Bc1, const float* __restrict__ Bc2,
       const float* __restrict__ Bc3,
       const float* __restrict__ bias,
       float* __restrict__ Cg, int ldc, long long sC, int K)
{
    extern __shared__ char smem[];
    const int tid  = threadIdx.x;
    const int z    = blockIdx.z;
    const int m0   = blockIdx.y * 128;
    const int n0   = blockIdx.x * 128;

    const uint32_t sbase = smem_u32(smem);
    const uint32_t data  = (sbase + 64 + 1023) & ~1023u;
    char* dptr = smem + (data - sbase);

    const float* A = Ag + (long long)(z / dA) * sA;
    const int nk = K >> 5;

    // B-source selector (shared by both paths)
    auto bsel = [&](int kc, const float*& bp, int& bld, int& bkc) {
        if (!CONV) {
            bp = Bg + (long long)(z / dB) * sB; bld = ldb; bkc = kc;
        } else {
            if      (kc < 512)  { bp = Bg  + (long long)z * ((long long)Pn * 512);        bld = 512; bkc = kc; }
            else if (kc < 1024) { bp = Bc1 + (long long)z * ((long long)Pn * 512);        bld = 512; bkc = kc - 512; }
            else if (kc < 1280) { bp = Bc2 + (long long)(z >> 2) * ((long long)Pn * 256); bld = 256; bkc = kc - 1024; }
            else                { bp = Bc3 + (long long)z * ((long long)Pn * 256);        bld = 256; bkc = kc - 1280; }
        }
    };

#if USE_TC
    // ======================= tcgen05 fast path (sm_103a) ====================
    const int wid  = tid >> 5;
    const int lane = tid & 31;
    const uint32_t hdr       = sbase;
    const uint32_t mb_full0  = hdr + 8;
    const uint32_t mb_empty0 = hdr + 32;
    const uint32_t mb_done   = hdr + 56;

    if (wid == 0) { TC_ALLOC(hdr, 128); TC_RELINQ(); }
    if (tid == 0) {
        #pragma unroll
        for (int s = 0; s < 3; ++s) {
            MBAR_INIT(mb_full0  + 8u * s, 256);
            MBAR_INIT(mb_empty0 + 8u * s, 1);
        }
        MBAR_INIT(mb_done, 1);
    }
    __syncthreads();
    uint32_t tmem;
    asm volatile("ld.shared.b32 %0, [%1];" : "=r"(tmem) : "r"(hdr));

    int ps = 0, pph = 1;   // producer stage/phase (first empty-wait passes)
    int cs = 0, cph = 0;   // consumer stage/phase (tid 0)

    for (int ch = 0; ch < nk; ++ch) {
        const int kc = ch << 5;

        // ---- producer: fill stage ps ----
        MBAR_WAIT(mb_empty0 + 8u * ps, pph);
        char* stg = dptr + ps * STAGE_B;

        #pragma unroll
        for (int i = 0; i < 4; ++i) {
            int u   = tid + i * 256;
            int row = u >> 3, c4 = u & 7;
            float4 v = *reinterpret_cast<const float4*>(
                A + (size_t)(m0 + row) * lda + kc + c4 * 4);
            float4 hi, lo;
            hi.x = to_tf32(v.x); lo.x = to_tf32(v.x - hi.x);
            hi.y = to_tf32(v.y); lo.y = to_tf32(v.y - hi.y);
            hi.z = to_tf32(v.z); lo.z = to_tf32(v.z - hi.z);
            hi.w = to_tf32(v.w); lo.w = to_tf32(v.w - hi.w);
            uint32_t off = sw128((uint32_t)(row * 128 + c4 * 16));
            *reinterpret_cast<float4*>(stg + off)          = hi;
            *reinterpret_cast<float4*>(stg + TILE_B + off) = lo;
        }

        const float* bp; int bld, bkc;
        bsel(kc, bp, bld, bkc);
        #pragma unroll
        for (int i = 0; i < 4; ++i) {
            int u   = tid + i * 256;
            int row = u >> 3, c4 = u & 7;
            float4 v = *reinterpret_cast<const float4*>(
                bp + (size_t)(n0 + row) * bld + bkc + c4 * 4);
            float4 hi, lo;
            hi.x = to_tf32(v.x); lo.x = to_tf32(v.x - hi.x);
            hi.y = to_tf32(v.y); lo.y = to_tf32(v.y - hi.y);
            hi.z = to_tf32(v.z); lo.z = to_tf32(v.z - hi.z);
            hi.w = to_tf32(v.w); lo.w = to_tf32(v.w - hi.w);
            uint32_t off = sw128((uint32_t)(row * 128 + c4 * 16));
            *reinterpret_cast<float4*>(stg + 2 * TILE_B + off) = hi;
            *reinterpret_cast<float4*>(stg + 3 * TILE_B + off) = lo;
        }

        FENCE_ASYNC();
        MBAR_ARRIVE(mb_full0 + 8u * ps);
        if (++ps == NSTAGE) { ps = 0; pph ^= 1; }

        // ---- consumer: issue MMAs for stage cs ----
        if (tid == 0) {
            MBAR_WAIT(mb_full0 + 8u * cs, cph);
            uint32_t sb = data + cs * STAGE_B;
            uint64_t ah = sdesc(sb);
            uint64_t al = sdesc(sb + TILE_B);
            uint64_t bh = sdesc(sb + 2 * TILE_B);
            uint64_t bl = sdesc(sb + 3 * TILE_B);
            #pragma unroll
            for (int ks = 0; ks < 4; ++ks) {
                uint64_t o = (uint64_t)(ks * 2);
                mma_tf32(tmem, ah + o, bh + o, !(ch == 0 && ks == 0));
                mma_tf32(tmem, ah + o, bl + o, true);
                mma_tf32(tmem, al + o, bh + o, true);
            }
            TC_COMMIT(ch == nk - 1 ? mb_done : (mb_empty0 + 8u * cs));
            if (++cs == NSTAGE) { cs = 0; cph ^= 1; }
        }
    }

    // ---- epilogue: TMEM -> smem (padded) -> coalesced gmem ----
    MBAR_WAIT(mb_done, 0);
    TC_FENCE_AFTER();

    float* sbuf = reinterpret_cast<float*>(dptr);  // 128 x 132 floats
    const int rsub = (wid & 3) * 32 + lane;
    const int g0   = (wid >> 2) * 2;

    #pragma unroll
    for (int gi = 0; gi < 2; ++gi) {
        const int g = g0 + gi;
        uint32_t r[32];
        TC_LD_X32(r, tmem + g * 32);
        TC_WAIT_LD();
        float rowb = (BIASM == 2) ? bias[m0 + rsub] : 0.0f;
        #pragma unroll
        for (int c4 = 0; c4 < 8; ++c4) {
            float4 v;
            v.x = __uint_as_float(r[c4 * 4 + 0]);
            v.y = __uint_as_float(r[c4 * 4 + 1]);
            v.z = __uint_as_float(r[c4 * 4 + 2]);
            v.w = __uint_as_float(r[c4 * 4 + 3]);
            if (BIASM == 1) {
                float4 bv = *reinterpret_cast<const float4*>(bias + n0 + g * 32 + c4 * 4);
                v.x += bv.x; v.y += bv.y; v.z += bv.z; v.w += bv.w;
            } else if (BIASM == 2) {
                v.x += rowb; v.y += rowb; v.z += rowb; v.w += rowb;
            }
            *reinterpret_cast<float4*>(&sbuf[rsub * 132 + g * 32 + c4 * 4]) = v;
        }
    }
    __syncthreads();

    float* C = Cg + (long long)z * sC;
    #pragma unroll
    for (int i = 0; i < 16; ++i) {
        int u   = tid + i * 256;
        int row = u >> 5, c4 = u & 31;
        float4 v = *reinterpret_cast<const float4*>(&sbuf[row * 132 + c4 * 4]);
        *reinterpret_cast<float4*>(C + (size_t)(m0 + row) * ldc + n0 + c4 * 4) = v;
    }

    __syncthreads();
    if (wid == 0) TC_DEALLOC(tmem, 128);

#else
    // ================== portable FFMA fallback (plain sm_103) ===============
    // Tiles stored kk-major in smem: As2[kk][m] (32 x 128), Bs2[kk][n].
    float* As2 = reinterpret_cast<float*>(dptr);
    float* Bs2 = As2 + 32 * 128;

    const int tx = tid & 15, ty = tid >> 4;
    float acc[8][8];
    #pragma unroll
    for (int i = 0; i < 8; ++i)
        #pragma unroll
        for (int j = 0; j < 8; ++j) acc[i][j] = 0.0f;

    for (int ch = 0; ch < nk; ++ch) {
        const int kc = ch << 5;
        __syncthreads();
        #pragma unroll
        for (int i = 0; i < 4; ++i) {
            int u = tid + i * 256;
            int row = u >> 3, c4 = u & 7;
            float4 v = *reinterpret_cast<const float4*>(
                A + (size_t)(m0 + row) * lda + kc + c4 * 4);
            As2[(c4 * 4 + 0) * 128 + row] = v.x;
            As2[(c4 * 4 + 1) * 128 + row] = v.y;
            As2[(c4 * 4 + 2) * 128 + row] = v.z;
            As2[(c4 * 4 + 3) * 128 + row] = v.w;
        }
        const float* bp; int bld, bkc;
        bsel(kc, bp, bld, bkc);
        #pragma unroll
        for (int i = 0; i < 4; ++i) {
            int u = tid + i * 256;
            int row = u >> 3, c4 = u & 7;
            float4 v = *reinterpret_cast<const float4*>(
                bp + (size_t)(n0 + row) * bld + bkc + c4 * 4);
            Bs2[(c4 * 4 + 0) * 128 + row] = v.x;
            Bs2[(c4 * 4 + 1) * 128 + row] = v.y;
            Bs2[(c4 * 4 + 2) * 128 + row] = v.z;
            Bs2[(c4 * 4 + 3) * 128 + row] = v.w;
        }
        __syncthreads();
        #pragma unroll
        for (int kk = 0; kk < 32; ++kk) {
            float a[8], b[8];
            #pragma unroll
            for (int i = 0; i < 4; ++i) {
                a[i]     = As2[kk * 128 + ty * 4 + i];
                a[i + 4] = As2[kk * 128 + 64 + ty * 4 + i];
                b[i]     = Bs2[kk * 128 + tx * 4 + i];
                b[i + 4] = Bs2[kk * 128 + 64 + tx * 4 + i];
            }
            #pragma unroll
            for (int i = 0; i < 8; ++i)
                #pragma unroll
                for (int j = 0; j < 8; ++j)
                    acc[i][j] = fmaf(a[i], b[j], acc[i][j]);
        }
    }

    float* C = Cg + (long long)z * sC;
    #pragma unroll
    for (int i = 0; i < 8; ++i) {
        const int m = m0 + ((i < 4) ? (ty * 4 + i) : (64 + ty * 4 + i - 4));
        const float rowb = (BIASM == 2) ? bias[m] : 0.0f;
        #pragma unroll
        for (int jh = 0; jh < 2; ++jh) {
            const int n = n0 + jh * 64 + tx * 4;
            float4 v;
            v.x = acc[i][jh * 4 + 0]; v.y = acc[i][jh * 4 + 1];
            v.z = acc[i][jh * 4 + 2]; v.w = acc[i][jh * 4 + 3];
            if (BIASM == 1) {
                float4 bv = *reinterpret_cast<const float4*>(bias + n);
                v.x += bv.x; v.y += bv.y; v.z += bv.z; v.w += bv.w;
            } else if (BIASM == 2) {
                v.x += rowb; v.y += rowb; v.z += rowb; v.w += rowb;
            }
            *reinterpret_cast<float4*>(C + (size_t)m * ldc + n) = v;
        }
    }
#endif
}

// ---------------------------------------------------------------------------
// 32x32 tiled transpose: src [z][C][Pn] -> dst [z][Pn][C]
// ---------------------------------------------------------------------------
__global__ void __launch_bounds__(256)
transp(const float* __restrict__ src, float* __restrict__ dst, int C)
{
    __shared__ float tile[32][33];
    const int p0 = blockIdx.x * 32, c0 = blockIdx.y * 32;
    const float* s = src + (size_t)blockIdx.z * C * Pn;
    float*       d = dst + (size_t)blockIdx.z * C * Pn;
    #pragma unroll
    for (int j = 0; j < 32; j += 8)
        tile[threadIdx.y + j][threadIdx.x] =
            s[(size_t)(c0 + threadIdx.y + j) * Pn + p0 + threadIdx.x];
    __syncthreads();
    #pragma unroll
    for (int j = 0; j < 32; j += 8)
        d[(size_t)(p0 + threadIdx.y + j) * C + c0 + threadIdx.x] =
            tile[threadIdx.x][threadIdx.y + j];
}

// ---------------------------------------------------------------------------
// Row softmax over g_S: grid (Pn, BN_), 256 threads, 9 elems/thread in regs
// ---------------------------------------------------------------------------
__global__ __launch_bounds__(256)
void softmax_rows(float* __restrict__ S)
{
    const int tid = threadIdx.x;
    const size_t base = ((size_t)blockIdx.y * Pn + blockIdx.x) * Pn;

    float r[9];
    float mx = -3.4e38f;
    #pragma unroll
    for (int j = 0; j < 9; ++j) {
        r[j] = S[base + tid + j * 256];
        mx = fmaxf(mx, r[j]);
    }
    __shared__ float sred[8];
    #pragma unroll
    for (int o = 16; o > 0; o >>= 1)
        mx = fmaxf(mx, __shfl_xor_sync(0xffffffffu, mx, o));
    if ((tid & 31) == 0) sred[tid >> 5] = mx;
    __syncthreads();
    mx = sred[0];
    #pragma unroll
    for (int w = 1; w < 8; ++w) mx = fmaxf(mx, sred[w]);

    float s = 0.0f;
    #pragma unroll
    for (int j = 0; j < 9; ++j) { r[j] = __expf(r[j] - mx); s += r[j]; }
    #pragma unroll
    for (int o = 16; o > 0; o >>= 1)
        s += __shfl_xor_sync(0xffffffffu, s, o);
    __syncthreads();
    if ((tid & 31) == 0) sred[tid >> 5] = s;
    __syncthreads();
    s = 0.0f;
    #pragma unroll
    for (int w = 0; w < 8; ++w) s += sred[w];

    const float inv = 1.0f / s;
    #pragma unroll
    for (int j = 0; j < 9; ++j)
        S[base + tid + j * 256] = r[j] * inv;
}

// ---------------------------------------------------------------------------
// Launch sequence (default stream, graph-capturable)
// ---------------------------------------------------------------------------
extern "C" void kernel_launch(void* const* d_in, const int* in_sizes, int n_in,
                              void* d_out, int out_size)
{
    const float* mv  = (const float*)d_in[0];   // [16,512,P]
    const float* ff  = (const float*)d_in[1];   // [4,256,P]
    const float* wq1 = (const float*)d_in[2];
    const float* bq1 = (const float*)d_in[3];
    const float* wk1 = (const float*)d_in[4];
    const float* bk1 = (const float*)d_in[5];
    const float* wq2 = (const float*)d_in[6];
    const float* bq2 = (const float*)d_in[7];
    const float* wk2 = (const float*)d_in[8];
    const float* bk2 = (const float*)d_in[9];
    const float* wdr = (const float*)d_in[10];  // [512,1536]
    const float* bdr = (const float*)d_in[11];
    float* out = (float*)d_out;                 // [16,512,P]

    float *mvT, *ffT, *Q1t, *K1t, *Q2t, *K2t, *S, *WRT, *WLT;
    cudaGetSymbolAddress((void**)&mvT, g_mvT);
    cudaGetSymbolAddress((void**)&ffT, g_ffT);
    cudaGetSymbolAddress((void**)&Q1t, g_Q1t);
    cudaGetSymbolAddress((void**)&K1t, g_K1t);
    cudaGetSymbolAddress((void**)&Q2t, g_Q2t);
    cudaGetSymbolAddress((void**)&K2t, g_K2t);
    cudaGetSymbolAddress((void**)&S,   g_S);
    cudaGetSymbolAddress((void**)&WRT, g_WRT);
    cudaGetSymbolAddress((void**)&WLT, g_WLT);

    cudaFuncSetAttribute(tfgemm<0, false>, cudaFuncAttributeMaxDynamicSharedMemorySize, SMEM_DYN);
    cudaFuncSetAttribute(tfgemm<1, false>, cudaFuncAttributeMaxDynamicSharedMemorySize, SMEM_DYN);
    cudaFuncSetAttribute(tfgemm<2, true>,  cudaFuncAttributeMaxDynamicSharedMemorySize, SMEM_DYN);

    const long long sMVT = (long long)Pn * CX_;
    const long long sFFT = (long long)Pn * CF_;
    const long long sHT  = (long long)Pn * HID_;
    const long long sS   = (long long)Pn * Pn;
    const long long sWRT = (long long)Pn * CF_;
    const long long sWLT = (long long)Pn * CX_;
    const long long sO   = (long long)OUT_ * Pn;

    // transposes -> K-major inputs
    transp<<<dim3(Pn / 32, CX_ / 32, 16), dim3(32, 8)>>>(mv, mvT, CX_);
    transp<<<dim3(Pn / 32, CF_ / 32, 4),  dim3(32, 8)>>>(ff, ffT, CF_);

    // projections: D[p,h] = sum_c X[p,c] * W[h,c] + b[h]
    tfgemm<1, false><<<dim3(2, 18, 16), 256, SMEM_DYN>>>(
        mvT, CX_, sMVT, 1,  wq1, CX_, 0LL, 1,  nullptr, nullptr, nullptr,
        bq1,  Q1t, HID_, sHT, CX_);
    tfgemm<1, false><<<dim3(2, 18, 4), 256, SMEM_DYN>>>(
        ffT, CF_, sFFT, 1,  wk1, CF_, 0LL, 1,  nullptr, nullptr, nullptr,
        bk1,  K1t, HID_, sHT, CF_);
    tfgemm<1, false><<<dim3(2, 18, 4), 256, SMEM_DYN>>>(
        ffT, CF_, sFFT, 1,  wq2, CF_, 0LL, 1,  nullptr, nullptr, nullptr,
        bq2,  Q2t, HID_, sHT, CF_);
    tfgemm<1, false><<<dim3(2, 18, 16), 256, SMEM_DYN>>>(
        mvT, CX_, sMVT, 1,  wk2, CX_, 0LL, 1,  nullptr, nullptr, nullptr,
        bk2,  K2t, HID_, sHT, CX_);

    // layer 1: S[p,q] = Q1t[p,:].K1t[q,:]; softmax; WRT[p,c] = S[p,:].ff[c,:]
    tfgemm<0, false><<<dim3(18, 18, 16), 256, SMEM_DYN>>>(
        Q1t, HID_, sHT, 1,  K1t, HID_, sHT, 4,  nullptr, nullptr, nullptr,
        nullptr,  S, Pn, sS, HID_);
    softmax_rows<<<dim3(Pn, BN_), 256>>>(S);
    tfgemm<0, false><<<dim3(2, 18, 16), 256, SMEM_DYN>>>(
        S, Pn, sS, 1,  ff, Pn, (long long)CF_ * Pn, 4,  nullptr, nullptr, nullptr,
        nullptr,  WRT, CF_, sWRT, Pn);

    // layer 2
    tfgemm<0, false><<<dim3(18, 18, 16), 256, SMEM_DYN>>>(
        Q2t, HID_, sHT, 4,  K2t, HID_, sHT, 1,  nullptr, nullptr, nullptr,
        nullptr,  S, Pn, sS, HID_);
    softmax_rows<<<dim3(Pn, BN_), 256>>>(S);
    tfgemm<0, false><<<dim3(4, 18, 16), 256, SMEM_DYN>>>(
        S, Pn, sS, 1,  mv, Pn, (long long)CX_ * Pn, 1,  nullptr, nullptr, nullptr,
        nullptr,  WLT, CX_, sWLT, Pn);

    // fused conv: out[o,p] = sum_f wdr[o,f] * featT[p,f] + bdr[o], K=1536
    tfgemm<2, true><<<dim3(18, 4, 16), 256, SMEM_DYN>>>(
        wdr, 1536, 0LL, 1,  mvT, 0, 0LL, 1,  WLT, ffT, WRT,
        bdr,  out, Pn, sO, 1536);
}

// round 12
// speedup vs baseline: 2.4416x; 1.1931x over previous
#include <cuda_runtime.h>
#include <cstdint>

// ---------------------------------------------------------------------------
// Arch gate: tcgen05 only exists on the arch-specific (sm_103a) target. The
// harness also compiles a plain compute_103 target, which must fall back.
// ---------------------------------------------------------------------------
#if defined(__CUDA_ARCH_FEAT_SM103_ALL) || defined(__CUDA_ARCH_FEAT_SM100_ALL) || \
    defined(__CUDA_ARCH_SPECIFIC__) || defined(__CUDA_ARCH_FAMILY_SPECIFIC__)
#define USE_TC 1
#else
#define USE_TC 0
#endif

// ---------------------------------------------------------------------------
// Problem constants
// ---------------------------------------------------------------------------
constexpr int Pn   = 48 * 48;   // 2304
constexpr int CX_  = 512;
constexpr int CF_  = 256;
constexpr int HID_ = 256;
constexpr int OUT_ = 512;
constexpr int BN_  = 16;

// ---------------------------------------------------------------------------
// Scratch (device globals; no allocation allowed). Everything K-major for its
// consumer GEMM.
// ---------------------------------------------------------------------------
__device__ float g_mvT[(size_t)BN_ * Pn * CX_];   // [z][p][cx]
__device__ float g_ffT[(size_t)4   * Pn * CF_];   // [b][p][cf]
__device__ float g_Q1t[(size_t)BN_ * Pn * HID_];  // [z][p][h]
__device__ float g_K1t[(size_t)4   * Pn * HID_];
__device__ float g_Q2t[(size_t)4   * Pn * HID_];
__device__ float g_K2t[(size_t)BN_ * Pn * HID_];
__device__ float g_S  [(size_t)BN_ * Pn * Pn];    // scores/attn (both layers)
__device__ float g_WRT[(size_t)BN_ * Pn * CF_];   // [z][p][cf]
__device__ float g_WLT[(size_t)BN_ * Pn * CX_];   // [z][p][cx]

// ---------------------------------------------------------------------------
// PTX helpers
// ---------------------------------------------------------------------------
__device__ __forceinline__ uint32_t smem_u32(const void* p) {
    uint32_t a;
    asm("{ .reg .u64 t; cvta.to.shared.u64 t, %1; cvt.u32.u64 %0, t; }"
        : "=r"(a) : "l"(p));
    return a;
}
// Bitmask hi/lo split: hi keeps the top 10 mantissa bits (tf32-exact), lo is
// the exact residual (|lo| < 2^-13 |x|); lo's own tf32 truncation leaves a
// ~2^-23 relative error. One LOP + one FSUB per element.
__device__ __forceinline__ void split2(float x, float& hi, float& lo) {
    hi = __uint_as_float(__float_as_uint(x) & 0xffffe000u);
    lo = x - hi;
}

#define MBAR_INIT(a, c) \
    asm volatile("mbarrier.init.shared.b64 [%0], %1;" :: "r"(a), "r"(c) : "memory")
#define MBAR_WAIT(a, ph) do {                                                  \
    uint32_t _m = (a), _p = (ph), _d = 0;                                      \
    while (!_d) {                                                              \
        asm volatile("{\n\t.reg .pred p;\n\t"                                  \
            "mbarrier.try_wait.parity.acquire.cta.shared::cta.b64 p, [%1], %2, 0x989680;\n\t" \
            "selp.b32 %0, 1, 0, p;\n\t}"                                       \
            : "=r"(_d) : "r"(_m), "r"(_p) : "memory");                         \
    } } while (0)

#define TC_ALLOC(sa, nc) \
    asm volatile("tcgen05.alloc.cta_group::1.sync.aligned.shared::cta.b32 [%0], %1;" \
        :: "r"(sa), "r"((uint32_t)(nc)) : "memory")
#define TC_RELINQ() \
    asm volatile("tcgen05.relinquish_alloc_permit.cta_group::1.sync.aligned;")
#define TC_DEALLOC(tm, nc) \
    asm volatile("tcgen05.dealloc.cta_group::1.sync.aligned.b32 %0, %1;" \
        :: "r"(tm), "r"((uint32_t)(nc)))
#define TC_COMMIT(mb) \
    asm volatile("tcgen05.commit.cta_group::1.mbarrier::arrive::one.shared::cluster.b64 [%0];" \
        :: "r"(mb) : "memory")
#define TC_FENCE_AFTER() asm volatile("tcgen05.fence::after_thread_sync;" ::: "memory")
#define TC_WAIT_LD()     asm volatile("tcgen05.wait::ld.sync.aligned;" ::: "memory")
#define FENCE_ASYNC()    asm volatile("fence.proxy.async.shared::cta;" ::: "memory")

#define TC_LD_X32(r, ta) \
    asm volatile("tcgen05.ld.sync.aligned.32x32b.x32.b32 " \
        "{%0,%1,%2,%3,%4,%5,%6,%7,%8,%9,%10,%11,%12,%13,%14,%15," \
        "%16,%17,%18,%19,%20,%21,%22,%23,%24,%25,%26,%27,%28,%29,%30,%31}, [%32];" \
        : "=r"((r)[0]),"=r"((r)[1]),"=r"((r)[2]),"=r"((r)[3]),   \
          "=r"((r)[4]),"=r"((r)[5]),"=r"((r)[6]),"=r"((r)[7]),   \
          "=r"((r)[8]),"=r"((r)[9]),"=r"((r)[10]),"=r"((r)[11]), \
          "=r"((r)[12]),"=r"((r)[13]),"=r"((r)[14]),"=r"((r)[15]),\
          "=r"((r)[16]),"=r"((r)[17]),"=r"((r)[18]),"=r"((r)[19]),\
          "=r"((r)[20]),"=r"((r)[21]),"=r"((r)[22]),"=r"((r)[23]),\
          "=r"((r)[24]),"=r"((r)[25]),"=r"((r)[26]),"=r"((r)[27]),\
          "=r"((r)[28]),"=r"((r)[29]),"=r"((r)[30]),"=r"((r)[31]) \
        : "r"(ta))

// idesc: D=F32(1<<4), A=TF32(2<<7), B=TF32(2<<10), N=128 (N/8 @17), M=128 (M/16 @24)
constexpr uint32_t IDESC_TF32 =
    (1u << 4) | (2u << 7) | (2u << 10) | ((128u / 8) << 17) | ((128u / 16) << 24);

__device__ __forceinline__ void mma_tf32(uint32_t d, uint64_t ad, uint64_t bd, bool acc) {
    asm volatile("{\n\t.reg .pred p;\n\tsetp.ne.u32 p, %5, 0;\n\t"
        "tcgen05.mma.cta_group::1.kind::tf32 [%0], %1, %2, %3, {%4,%4,%4,%4}, p;\n\t}"
        :: "r"(d), "l"(ad), "l"(bd), "r"(IDESC_TF32), "r"(0u), "r"(acc ? 1u : 0u)
        : "memory");
}

// SW128 K-major smem descriptor: layout=2, version=1, SBO=64, LBO=1
constexpr uint64_t DESC_BASE =
    (2ull << 61) | (1ull << 46) | (64ull << 32) | (1ull << 16);
__device__ __forceinline__ uint64_t sdesc(uint32_t addr) {
    return DESC_BASE | ((uint64_t)(addr >> 4) & 0x3FFFull);
}
__device__ __forceinline__ uint32_t sw128(uint32_t off) {
    return off ^ ((off >> 3) & 0x70);
}

// smem: 64B header (tmem ptr @0; done-mbar[s] @8+8s), then 1024-aligned data:
// 3 stages x 64KB (Ahi|Alo|Bhi|Blo 16KB each).
constexpr int TILE_B    = 16384;
constexpr int STAGE_B   = 4 * TILE_B;
constexpr int NSTAGE    = 3;
constexpr int SMEM_DYN  = 1024 + NSTAGE * STAGE_B + 1024;

// ---------------------------------------------------------------------------
// Batched GEMM: D[m,n] = sum_k A[m,k] * B[n,k]; A,B K-major in gmem.
// Tile 128x128, K-chunk 32.  BIASM: 0 none, 1 bias[n], 2 bias[m].
// CONV: B rows gathered from concat(Bg=mvT | Bc1=WLT | Bc2=ffT | Bc3=WRT).
// Sync per chunk: __syncthreads (producers done) -> tid0 fence + 12 MMA
// dispatches + commit(done[stage]); stage recycled after all threads observe
// the commit (wait-only, single arrival -- no 256-thread arrive storm).
// ---------------------------------------------------------------------------
template<int BIASM, bool CONV>
__global__ void __launch_bounds__(256, 1)
tfgemm(const float* __restrict__ Ag, int lda, long long sA, int dA,
       const float* __restrict__ Bg, int ldb, long long sB, int dB,
       const float* __restrict__ Bc1, const float* __restrict__ Bc2,
       const float* __restrict__ Bc3,
       const float* __restrict__ bias,
       float* __restrict__ Cg, int ldc, long long sC, int K)
{
    extern __shared__ char smem[];
    const int tid  = threadIdx.x;
    const int z    = blockIdx.z;
    const int m0   = blockIdx.y * 128;
    const int n0   = blockIdx.x * 128;

    const uint32_t sbase = smem_u32(smem);
    const uint32_t data  = (sbase + 64 + 1023) & ~1023u;
    char* dptr = smem + (data - sbase);

    const float* A = Ag + (long long)(z / dA) * sA;
    const int nk = K >> 5;

    // B-source selector (per k-chunk base)
    auto bsel = [&](int kc, const float*& bp, int& bld, int& bkc) {
        if (!CONV) {
            bp = Bg + (long long)(z / dB) * sB; bld = ldb; bkc = kc;
        } else {
            if      (kc < 512)  { bp = Bg  + (long long)z * ((long long)Pn * 512);        bld = 512; bkc = kc; }
            else if (kc < 1024) { bp = Bc1 + (long long)z * ((long long)Pn * 512);        bld = 512; bkc = kc - 512; }
            else if (kc < 1280) { bp = Bc2 + (long long)(z >> 2) * ((long long)Pn * 256); bld = 256; bkc = kc - 1024; }
            else                { bp = Bc3 + (long long)z * ((long long)Pn * 256);        bld = 256; bkc = kc - 1280; }
        }
    };

#if USE_TC
    // ======================= tcgen05 fast path (sm_103a) ====================
    const int wid  = tid >> 5;
    const int lane = tid & 31;
    const uint32_t hdr   = sbase;
    const uint32_t done0 = hdr + 8;     // 3 mbarriers, one per stage

    if (wid == 0) { TC_ALLOC(hdr, 128); TC_RELINQ(); }
    if (tid == 0) {
        #pragma unroll
        for (int s = 0; s < NSTAGE; ++s) MBAR_INIT(done0 + 8u * s, 1);
    }
    __syncthreads();
    uint32_t tmem;
    asm volatile("ld.shared.b32 %0, [%1];" : "=r"(tmem) : "r"(hdr));

    // chunk-invariant producer indexing: thread owns rows r0+32i, float4 col c4
    const int c4 = tid & 7;
    const int r0 = tid >> 3;
    uint32_t soff[4];
    #pragma unroll
    for (int i = 0; i < 4; ++i)
        soff[i] = sw128((uint32_t)((r0 + i * 32) * 128 + c4 * 16));
    const float* aptr = A + (size_t)(m0 + r0) * lda + c4 * 4;
    const size_t  astr = (size_t)32 * lda;
    const float* bptr0 = nullptr;
    size_t bstr = 0;
    if (!CONV) {
        bptr0 = Bg + (long long)(z / dB) * sB + (size_t)(n0 + r0) * ldb + c4 * 4;
        bstr  = (size_t)32 * ldb;
    }

    int ps = 0, rr = 0;   // stage index, wrap-round counter
    for (int ch = 0; ch < nk; ++ch) {
        const int kc = ch << 5;

        // issue gmem loads first (hide latency behind the stage-recycle wait)
        float4 va[4], vb[4];
        #pragma unroll
        for (int i = 0; i < 4; ++i)
            va[i] = *reinterpret_cast<const float4*>(aptr + kc + (size_t)i * astr);
        if (!CONV) {
            #pragma unroll
            for (int i = 0; i < 4; ++i)
                vb[i] = *reinterpret_cast<const float4*>(bptr0 + kc + (size_t)i * bstr);
        } else {
            const float* bp; int bld, bkc;
            bsel(kc, bp, bld, bkc);
            const float* bt = bp + (size_t)(n0 + r0) * bld + bkc + c4 * 4;
            #pragma unroll
            for (int i = 0; i < 4; ++i)
                vb[i] = *reinterpret_cast<const float4*>(bt + (size_t)i * 32 * bld);
        }

        // stage recycle: MMA that read this stage (chunk ch-NSTAGE) committed
        if (rr > 0) MBAR_WAIT(done0 + 8u * ps, (rr - 1) & 1);

        char* stg = dptr + ps * STAGE_B;
        #pragma unroll
        for (int i = 0; i < 4; ++i) {
            float4 hi, lo;
            split2(va[i].x, hi.x, lo.x); split2(va[i].y, hi.y, lo.y);
            split2(va[i].z, hi.z, lo.z); split2(va[i].w, hi.w, lo.w);
            *reinterpret_cast<float4*>(stg + soff[i])          = hi;
            *reinterpret_cast<float4*>(stg + TILE_B + soff[i]) = lo;
        }
        #pragma unroll
        for (int i = 0; i < 4; ++i) {
            float4 hi, lo;
            split2(vb[i].x, hi.x, lo.x); split2(vb[i].y, hi.y, lo.y);
            split2(vb[i].z, hi.z, lo.z); split2(vb[i].w, hi.w, lo.w);
            *reinterpret_cast<float4*>(stg + 2 * TILE_B + soff[i]) = hi;
            *reinterpret_cast<float4*>(stg + 3 * TILE_B + soff[i]) = lo;
        }

        __syncthreads();   // all producer stores for this stage are done

        if (tid == 0) {
            FENCE_ASYNC();
            uint32_t sb = data + ps * STAGE_B;
            uint64_t ah = sdesc(sb);
            uint64_t al = sdesc(sb + TILE_B);
            uint64_t bh = sdesc(sb + 2 * TILE_B);
            uint64_t bl = sdesc(sb + 3 * TILE_B);
            #pragma unroll
            for (int ks = 0; ks < 4; ++ks) {
                uint64_t o = (uint64_t)(ks * 2);
                mma_tf32(tmem, ah + o, bh + o, !(ch == 0 && ks == 0));
                mma_tf32(tmem, ah + o, bl + o, true);
                mma_tf32(tmem, al + o, bh + o, true);
            }
            TC_COMMIT(done0 + 8u * ps);
        }
        if (++ps == NSTAGE) { ps = 0; ++rr; }
    }

    // final commit covers all prior MMAs (commit waits on all earlier MMAs)
    MBAR_WAIT(done0 + 8u * ((nk - 1) % NSTAGE), ((nk - 1) / NSTAGE) & 1);
    TC_FENCE_AFTER();

    // ---- epilogue: TMEM -> smem (padded) -> coalesced gmem ----
    float* sbuf = reinterpret_cast<float*>(dptr);  // 128 x 132 floats
    const int rsub = (wid & 3) * 32 + lane;
    const int g0   = (wid >> 2) * 2;

    #pragma unroll
    for (int gi = 0; gi < 2; ++gi) {
        const int g = g0 + gi;
        uint32_t r[32];
        TC_LD_X32(r, tmem + g * 32);
        TC_WAIT_LD();
        float rowb = (BIASM == 2) ? bias[m0 + rsub] : 0.0f;
        #pragma unroll
        for (int cc = 0; cc < 8; ++cc) {
            float4 v;
            v.x = __uint_as_float(r[cc * 4 + 0]);
            v.y = __uint_as_float(r[cc * 4 + 1]);
            v.z = __uint_as_float(r[cc * 4 + 2]);
            v.w = __uint_as_float(r[cc * 4 + 3]);
            if (BIASM == 1) {
                float4 bv = *reinterpret_cast<const float4*>(bias + n0 + g * 32 + cc * 4);
                v.x += bv.x; v.y += bv.y; v.z += bv.z; v.w += bv.w;
            } else if (BIASM == 2) {
                v.x += rowb; v.y += rowb; v.z += rowb; v.w += rowb;
            }
            *reinterpret_cast<float4*>(&sbuf[rsub * 132 + g * 32 + cc * 4]) = v;
        }
    }
    __syncthreads();

    float* C = Cg + (long long)z * sC;
    #pragma unroll
    for (int i = 0; i < 16; ++i) {
        int u   = tid + i * 256;
        int row = u >> 5, cc = u & 31;
        float4 v = *reinterpret_cast<const float4*>(&sbuf[row * 132 + cc * 4]);
        *reinterpret_cast<float4*>(C + (size_t)(m0 + row) * ldc + n0 + cc * 4) = v;
    }

    __syncthreads();
    if (wid == 0) TC_DEALLOC(tmem, 128);

#else
    // ================== portable FFMA fallback (plain sm_103) ===============
    float* As2 = reinterpret_cast<float*>(dptr);
    float* Bs2 = As2 + 32 * 128;

    const int tx = tid & 15, ty = tid >> 4;
    float acc[8][8];
    #pragma unroll
    for (int i = 0; i < 8; ++i)
        #pragma unroll
        for (int j = 0; j < 8; ++j) acc[i][j] = 0.0f;

    for (int ch = 0; ch < nk; ++ch) {
        const int kc = ch << 5;
        __syncthreads();
        #pragma unroll
        for (int i = 0; i < 4; ++i) {
            int u = tid + i * 256;
            int row = u >> 3, cc = u & 7;
            float4 v = *reinterpret_cast<const float4*>(
                A + (size_t)(m0 + row) * lda + kc + cc * 4);
            As2[(cc * 4 + 0) * 128 + row] = v.x;
            As2[(cc * 4 + 1) * 128 + row] = v.y;
            As2[(cc * 4 + 2) * 128 + row] = v.z;
            As2[(cc * 4 + 3) * 128 + row] = v.w;
        }
        const float* bp; int bld, bkc;
        bsel(kc, bp, bld, bkc);
        #pragma unroll
        for (int i = 0; i < 4; ++i) {
            int u = tid + i * 256;
            int row = u >> 3, cc = u & 7;
            float4 v = *reinterpret_cast<const float4*>(
                bp + (size_t)(n0 + row) * bld + bkc + cc * 4);
            Bs2[(cc * 4 + 0) * 128 + row] = v.x;
            Bs2[(cc * 4 + 1) * 128 + row] = v.y;
            Bs2[(cc * 4 + 2) * 128 + row] = v.z;
            Bs2[(cc * 4 + 3) * 128 + row] = v.w;
        }
        __syncthreads();
        #pragma unroll
        for (int kk = 0; kk < 32; ++kk) {
            float a[8], b[8];
            #pragma unroll
            for (int i = 0; i < 4; ++i) {
                a[i]     = As2[kk * 128 + ty * 4 + i];
                a[i + 4] = As2[kk * 128 + 64 + ty * 4 + i];
                b[i]     = Bs2[kk * 128 + tx * 4 + i];
                b[i + 4] = Bs2[kk * 128 + 64 + tx * 4 + i];
            }
            #pragma unroll
            for (int i = 0; i < 8; ++i)
                #pragma unroll
                for (int j = 0; j < 8; ++j)
                    acc[i][j] = fmaf(a[i], b[j], acc[i][j]);
        }
    }

    float* C = Cg + (long long)z * sC;
    #pragma unroll
    for (int i = 0; i < 8; ++i) {
        const int m = m0 + ((i < 4) ? (ty * 4 + i) : (64 + ty * 4 + i - 4));
        const float rowb = (BIASM == 2) ? bias[m] : 0.0f;
        #pragma unroll
        for (int jh = 0; jh < 2; ++jh) {
            const int n = n0 + jh * 64 + tx * 4;
            float4 v;
            v.x = acc[i][jh * 4 + 0]; v.y = acc[i][jh * 4 + 1];
            v.z = acc[i][jh * 4 + 2]; v.w = acc[i][jh * 4 + 3];
            if (BIASM == 1) {
                float4 bv = *reinterpret_cast<const float4*>(bias + n);
                v.x += bv.x; v.y += bv.y; v.z += bv.z; v.w += bv.w;
            } else if (BIASM == 2) {
                v.x += rowb; v.y += rowb; v.z += rowb; v.w += rowb;
            }
            *reinterpret_cast<float4*>(C + (size_t)m * ldc + n) = v;
        }
    }
#endif
}

// ---------------------------------------------------------------------------
// 32x32 tiled transpose: src [z][C][Pn] -> dst [z][Pn][C]
// ---------------------------------------------------------------------------
__global__ void __launch_bounds__(256)
transp(const float* __restrict__ src, float* __restrict__ dst, int C)
{
    __shared__ float tile[32][33];
    const int p0 = blockIdx.x * 32, c0 = blockIdx.y * 32;
    const float* s = src + (size_t)blockIdx.z * C * Pn;
    float*       d = dst + (size_t)blockIdx.z * C * Pn;
    #pragma unroll
    for (int j = 0; j < 32; j += 8)
        tile[threadIdx.y + j][threadIdx.x] =
            s[(size_t)(c0 + threadIdx.y + j) * Pn + p0 + threadIdx.x];
    __syncthreads();
    #pragma unroll
    for (int j = 0; j < 32; j += 8)
        d[(size_t)(p0 + threadIdx.y + j) * C + c0 + threadIdx.x] =
            tile[threadIdx.x][threadIdx.y + j];
}

// ---------------------------------------------------------------------------
// Row softmax over g_S: grid (Pn, BN_), 256 threads, 9 elems/thread in regs
// ---------------------------------------------------------------------------
__global__ __launch_bounds__(256)
void softmax_rows(float* __restrict__ S)
{
    const int tid = threadIdx.x;
    const size_t base = ((size_t)blockIdx.y * Pn + blockIdx.x) * Pn;

    float r[9];
    float mx = -3.4e38f;
    #pragma unroll
    for (int j = 0; j < 9; ++j) {
        r[j] = S[base + tid + j * 256];
        mx = fmaxf(mx, r[j]);
    }
    __shared__ float sred[8];
    #pragma unroll
    for (int o = 16; o > 0; o >>= 1)
        mx = fmaxf(mx, __shfl_xor_sync(0xffffffffu, mx, o));
    if ((tid & 31) == 0) sred[tid >> 5] = mx;
    __syncthreads();
    mx = sred[0];
    #pragma unroll
    for (int w = 1; w < 8; ++w) mx = fmaxf(mx, sred[w]);

    float s = 0.0f;
    #pragma unroll
    for (int j = 0; j < 9; ++j) { r[j] = __expf(r[j] - mx); s += r[j]; }
    #pragma unroll
    for (int o = 16; o > 0; o >>= 1)
        s += __shfl_xor_sync(0xffffffffu, s, o);
    __syncthreads();
    if ((tid & 31) == 0) sred[tid >> 5] = s;
    __syncthreads();
    s = 0.0f;
    #pragma unroll
    for (int w = 0; w < 8; ++w) s += sred[w];

    const float inv = 1.0f / s;
    #pragma unroll
    for (int j = 0; j < 9; ++j)
        S[base + tid + j * 256] = r[j] * inv;
}

// ---------------------------------------------------------------------------
// Launch sequence (default stream, graph-capturable)
// ---------------------------------------------------------------------------
extern "C" void kernel_launch(void* const* d_in, const int* in_sizes, int n_in,
                              void* d_out, int out_size)
{
    const float* mv  = (const float*)d_in[0];   // [16,512,P]
    const float* ff  = (const float*)d_in[1];   // [4,256,P]
    const float* wq1 = (const float*)d_in[2];
    const float* bq1 = (const float*)d_in[3];
    const float* wk1 = (const float*)d_in[4];
    const float* bk1 = (const float*)d_in[5];
    const float* wq2 = (const float*)d_in[6];
    const float* bq2 = (const float*)d_in[7];
    const float* wk2 = (const float*)d_in[8];
    const float* bk2 = (const float*)d_in[9];
    const float* wdr = (const float*)d_in[10];  // [512,1536]
    const float* bdr = (const float*)d_in[11];
    float* out = (float*)d_out;                 // [16,512,P]

    float *mvT, *ffT, *Q1t, *K1t, *Q2t, *K2t, *S, *WRT, *WLT;
    cudaGetSymbolAddress((void**)&mvT, g_mvT);
    cudaGetSymbolAddress((void**)&ffT, g_ffT);
    cudaGetSymbolAddress((void**)&Q1t, g_Q1t);
    cudaGetSymbolAddress((void**)&K1t, g_K1t);
    cudaGetSymbolAddress((void**)&Q2t, g_Q2t);
    cudaGetSymbolAddress((void**)&K2t, g_K2t);
    cudaGetSymbolAddress((void**)&S,   g_S);
    cudaGetSymbolAddress((void**)&WRT, g_WRT);
    cudaGetSymbolAddress((void**)&WLT, g_WLT);

    cudaFuncSetAttribute(tfgemm<0, false>, cudaFuncAttributeMaxDynamicSharedMemorySize, SMEM_DYN);
    cudaFuncSetAttribute(tfgemm<1, false>, cudaFuncAttributeMaxDynamicSharedMemorySize, SMEM_DYN);
    cudaFuncSetAttribute(tfgemm<2, true>,  cudaFuncAttributeMaxDynamicSharedMemorySize, SMEM_DYN);

    const long long sMVT = (long long)Pn * CX_;
    const long long sFFT = (long long)Pn * CF_;
    const long long sHT  = (long long)Pn * HID_;
    const long long sS   = (long long)Pn * Pn;
    const long long sWRT = (long long)Pn * CF_;
    const long long sWLT = (long long)Pn * CX_;
    const long long sO   = (long long)OUT_ * Pn;

    // transposes -> K-major inputs
    transp<<<dim3(Pn / 32, CX_ / 32, 16), dim3(32, 8)>>>(mv, mvT, CX_);
    transp<<<dim3(Pn / 32, CF_ / 32, 4),  dim3(32, 8)>>>(ff, ffT, CF_);

    // projections: D[p,h] = sum_c X[p,c] * W[h,c] + b[h]
    tfgemm<1, false><<<dim3(2, 18, 16), 256, SMEM_DYN>>>(
        mvT, CX_, sMVT, 1,  wq1, CX_, 0LL, 1,  nullptr, nullptr, nullptr,
        bq1,  Q1t, HID_, sHT, CX_);
    tfgemm<1, false><<<dim3(2, 18, 4), 256, SMEM_DYN>>>(
        ffT, CF_, sFFT, 1,  wk1, CF_, 0LL, 1,  nullptr, nullptr, nullptr,
        bk1,  K1t, HID_, sHT, CF_);
    tfgemm<1, false><<<dim3(2, 18, 4), 256, SMEM_DYN>>>(
        ffT, CF_, sFFT, 1,  wq2, CF_, 0LL, 1,  nullptr, nullptr, nullptr,
        bq2,  Q2t, HID_, sHT, CF_);
    tfgemm<1, false><<<dim3(2, 18, 16), 256, SMEM_DYN>>>(
        mvT, CX_, sMVT, 1,  wk2, CX_, 0LL, 1,  nullptr, nullptr, nullptr,
        bk2,  K2t, HID_, sHT, CX_);

    // layer 1: S[p,q] = Q1t[p,:].K1t[q,:]; softmax; WRT[p,c] = S[p,:].ff[c,:]
    tfgemm<0, false><<<dim3(18, 18, 16), 256, SMEM_DYN>>>(
        Q1t, HID_, sHT, 1,  K1t, HID_, sHT, 4,  nullptr, nullptr, nullptr,
        nullptr,  S, Pn, sS, HID_);
    softmax_rows<<<dim3(Pn, BN_), 256>>>(S);
    tfgemm<0, false><<<dim3(2, 18, 16), 256, SMEM_DYN>>>(
        S, Pn, sS, 1,  ff, Pn, (long long)CF_ * Pn, 4,  nullptr, nullptr, nullptr,
        nullptr,  WRT, CF_, sWRT, Pn);

    // layer 2
    tfgemm<0, false><<<dim3(18, 18, 16), 256, SMEM_DYN>>>(
        Q2t, HID_, sHT, 4,  K2t, HID_, sHT, 1,  nullptr, nullptr, nullptr,
        nullptr,  S, Pn, sS, HID_);
    softmax_rows<<<dim3(Pn, BN_), 256>>>(S);
    tfgemm<0, false><<<dim3(4, 18, 16), 256, SMEM_DYN>>>(
        S, Pn, sS, 1,  mv, Pn, (long long)CX_ * Pn, 1,  nullptr, nullptr, nullptr,
        nullptr,  WLT, CX_, sWLT, Pn);

    // fused conv: out[o,p] = sum_f wdr[o,f] * featT[p,f] + bdr[o], K=1536
    tfgemm<2, true><<<dim3(18, 4, 16), 256, SMEM_DYN>>>(
        wdr, 1536, 0LL, 1,  mvT, 0, 0LL, 1,  WLT, ffT, WRT,
        bdr,  out, Pn, sO, 1536);
}